// round 3
// baseline (speedup 1.0000x reference)
#include <cuda_runtime.h>
#include <math.h>

#define B_    64
#define T_    50000
#define C_    4
#define MSYN  4
#define D_    160
#define PATCH 25
#define L_    2000        // T_/PATCH
#define KENV  25
#define KBUR  9
#define KPRE  9

#define TILE  500
#define HALO  16
#define NTHR1 128

#define G2    4
#define NTHR2 160
#define NGROUP (B_ * L_ / G2)   // 32000

// xs[b][t] stored as float4 over the 4 synergy channels
__device__ float4 g_xs[(size_t)B_ * T_];

__device__ __forceinline__ float softplusf_(float v) {
    // stable: max(v,0) + log1p(exp(-|v|))
    return fmaxf(v, 0.0f) + log1pf(expf(-fabsf(v)));
}
__device__ __forceinline__ float gelu_exact(float v) {
    // x * Phi(x) == 0.5*x*(1+erf(x/sqrt(2)))
    return v * normcdff(v);
}

// ---------------------------------------------------------------------------
// Stage 1: fused front pipeline -> xs scratch + m_patch
// ---------------------------------------------------------------------------
__global__ __launch_bounds__(NTHR1) void stage1_kernel(
    const float4* __restrict__ X, const float4* __restrict__ M,
    const float*  __restrict__ w_env, const float* __restrict__ w_burst,
    const float*  __restrict__ synergy_raw, const float* __restrict__ w_pre_dw,
    const float*  __restrict__ w_pre_pw, float* __restrict__ out_mpatch)
{
    __shared__ float4 sx [TILE + 2*HALO];  // x = X*M at t0-16+j
    __shared__ float4 sdx[TILE + 16];      // |dx|   at t0-8+i
    __shared__ float4 sm4[TILE];           // M at t0+i
    __shared__ float4 sS0[TILE + 8];       // S0 at t0-4+i
    __shared__ float  smt[TILE];           // m_time
    __shared__ float4 swe[KENV], swb[KBUR], swd[KPRE];

    const int tid  = threadIdx.x;
    const int tile = blockIdx.x;
    const int b    = blockIdx.y;
    const int t0   = tile * TILE;

    if (tid < KENV) swe[tid] = make_float4(w_env[tid], w_env[25+tid], w_env[50+tid], w_env[75+tid]);
    if (tid < KBUR) swb[tid] = make_float4(w_burst[tid], w_burst[9+tid], w_burst[18+tid], w_burst[27+tid]);
    if (tid < KPRE) swd[tid] = make_float4(w_pre_dw[tid], w_pre_dw[9+tid], w_pre_dw[18+tid], w_pre_dw[27+tid]);

    // Normalized synergy matrix W and pointwise weights (registers, every thread)
    float Wm[4][4];
    #pragma unroll
    for (int m = 0; m < 4; m++) {
        float r0 = softplusf_(synergy_raw[m*4+0]);
        float r1 = softplusf_(synergy_raw[m*4+1]);
        float r2 = softplusf_(synergy_raw[m*4+2]);
        float r3 = softplusf_(synergy_raw[m*4+3]);
        float inv = 1.0f / fmaxf(r0+r1+r2+r3, 1e-6f);
        Wm[m][0]=r0*inv; Wm[m][1]=r1*inv; Wm[m][2]=r2*inv; Wm[m][3]=r3*inv;
    }
    float pw[4][4];
    #pragma unroll
    for (int o = 0; o < 4; o++)
        #pragma unroll
        for (int m = 0; m < 4; m++)
            pw[o][m] = w_pre_pw[o*4+m];

    // Phase A: load x = X*M with halo (zero padded), keep interior M for Sm
    const float4* Xb = X + (size_t)b * T_;
    const float4* Mb = M + (size_t)b * T_;
    for (int j = tid; j < TILE + 2*HALO; j += NTHR1) {
        int t = t0 - HALO + j;
        float4 v = make_float4(0.f,0.f,0.f,0.f);
        if (t >= 0 && t < T_) {
            float4 xv = Xb[t];
            float4 mv = Mb[t];
            v.x = xv.x*mv.x; v.y = xv.y*mv.y; v.z = xv.z*mv.z; v.w = xv.w*mv.w;
            if (j >= HALO && j < HALO + TILE) sm4[j - HALO] = mv;
        }
        sx[j] = v;
    }
    __syncthreads();

    // Phase dx: |x[t]-x[t-1]|, 0 outside [1, T)
    for (int i = tid; i < TILE + 16; i += NTHR1) {
        int t = t0 - 8 + i;
        float4 v = make_float4(0.f,0.f,0.f,0.f);
        if (t >= 1 && t < T_) {
            float4 a = sx[i+8], c = sx[i+7];
            v.x = fabsf(a.x-c.x); v.y = fabsf(a.y-c.y);
            v.z = fabsf(a.z-c.z); v.w = fabsf(a.w-c.w);
        }
        sdx[i] = v;
    }
    __syncthreads();

    // Phase B: env, burst, xm, S0 (with 4-halo), zero outside [0,T)
    for (int i = tid; i < TILE + 8; i += NTHR1) {
        int t = t0 - 4 + i;
        float4 s0 = make_float4(0.f,0.f,0.f,0.f);
        if (t >= 0 && t < T_) {
            float4 env = make_float4(0.f,0.f,0.f,0.f);
            #pragma unroll
            for (int k = 0; k < KENV; k++) {
                float4 xv = sx[i + k]; float4 w = swe[k];
                env.x = fmaf(fabsf(xv.x), w.x, env.x);
                env.y = fmaf(fabsf(xv.y), w.y, env.y);
                env.z = fmaf(fabsf(xv.z), w.z, env.z);
                env.w = fmaf(fabsf(xv.w), w.w, env.w);
            }
            float4 bur = make_float4(0.f,0.f,0.f,0.f);
            #pragma unroll
            for (int k = 0; k < KBUR; k++) {
                float4 dv = sdx[i + k]; float4 w = swb[k];
                bur.x = fmaf(dv.x, w.x, bur.x);
                bur.y = fmaf(dv.y, w.y, bur.y);
                bur.z = fmaf(dv.z, w.z, bur.z);
                bur.w = fmaf(dv.w, w.w, bur.w);
            }
            float4 xv = sx[i + 12];
            float xm0 = 0.9f*env.x + 0.6f*bur.x + 0.2f*xv.x;
            float xm1 = 0.9f*env.y + 0.6f*bur.y + 0.2f*xv.y;
            float xm2 = 0.9f*env.z + 0.6f*bur.z + 0.2f*xv.z;
            float xm3 = 0.9f*env.w + 0.6f*bur.w + 0.2f*xv.w;
            s0.x = Wm[0][0]*xm0 + Wm[0][1]*xm1 + Wm[0][2]*xm2 + Wm[0][3]*xm3;
            s0.y = Wm[1][0]*xm0 + Wm[1][1]*xm1 + Wm[1][2]*xm2 + Wm[1][3]*xm3;
            s0.z = Wm[2][0]*xm0 + Wm[2][1]*xm1 + Wm[2][2]*xm2 + Wm[2][3]*xm3;
            s0.w = Wm[3][0]*xm0 + Wm[3][1]*xm1 + Wm[3][2]*xm2 + Wm[3][3]*xm3;
        }
        sS0[i] = s0;
    }
    __syncthreads();

    // Phase C: S1 (dwconv K=9 + gelu), S2 (pointwise + gelu), Sm, xs, m_time
    for (int i = tid; i < TILE; i += NTHR1) {
        int t = t0 + i;
        float a0=0.f,a1=0.f,a2=0.f,a3=0.f;
        #pragma unroll
        for (int k = 0; k < KPRE; k++) {
            float4 sv = sS0[i + k]; float4 w = swd[k];
            a0 = fmaf(sv.x, w.x, a0);
            a1 = fmaf(sv.y, w.y, a1);
            a2 = fmaf(sv.z, w.z, a2);
            a3 = fmaf(sv.w, w.w, a3);
        }
        float s1[4];
        s1[0] = gelu_exact(a0); s1[1] = gelu_exact(a1);
        s1[2] = gelu_exact(a2); s1[3] = gelu_exact(a3);

        float s2[4];
        #pragma unroll
        for (int o = 0; o < 4; o++) {
            float v = pw[o][0]*s1[0] + pw[o][1]*s1[1] + pw[o][2]*s1[2] + pw[o][3]*s1[3];
            s2[o] = gelu_exact(v);
        }

        float4 mv = sm4[i];
        float mm0 = (mv.x > 0.f) ? 1.f : 0.f;
        float mm1 = (mv.y > 0.f) ? 1.f : 0.f;
        float mm2 = (mv.z > 0.f) ? 1.f : 0.f;
        float mm3 = (mv.w > 0.f) ? 1.f : 0.f;
        float smv[4];
        #pragma unroll
        for (int m = 0; m < 4; m++) {
            float v = Wm[m][0]*mm0 + Wm[m][1]*mm1 + Wm[m][2]*mm2 + Wm[m][3]*mm3;
            smv[m] = fminf(fmaxf(v, 0.0f), 1.0f);
        }

        float4 xs = make_float4(s2[0]*smv[0], s2[1]*smv[1], s2[2]*smv[2], s2[3]*smv[3]);
        g_xs[(size_t)b * T_ + t] = xs;
        smt[i] = ((smv[0]+smv[1]+smv[2]+smv[3]) > 0.0f) ? 1.0f : 0.0f;
    }
    __syncthreads();

    // m_patch: 20 patches per tile
    if (tid < TILE / PATCH) {
        float s = 0.f;
        int base = tid * PATCH;
        #pragma unroll
        for (int p = 0; p < PATCH; p++) s += smt[base + p];
        out_mpatch[b * L_ + tile * (TILE/PATCH) + tid] =
            (s * (1.0f/25.0f) > 0.1f) ? 1.0f : 0.0f;
    }
}

// ---------------------------------------------------------------------------
// Stage 2: [128000 x 100] x [100 x 160] projection + LayerNorm(160)
// persistent blocks, thread = output channel d, weights in f32x2-packed regs
// ---------------------------------------------------------------------------
__global__ __launch_bounds__(NTHR2) void stage2_kernel(
    const float* __restrict__ w_proj, const float* __restrict__ ln_gamma,
    const float* __restrict__ ln_beta, float* __restrict__ out_h)
{
    __shared__ float s[G2][100];     // patch data, row = 400B = 16B-aligned
    __shared__ float red[5][2*G2];   // per-warp partials (sum, sumsq)
    __shared__ float stats[G2][2];   // mu, rsigma

    const int tid  = threadIdx.x;
    const int d    = tid;
    const int lane = tid & 31;
    const int warp = tid >> 5;

    // Pack w_proj[d, m, p] into 50 f32x2 registers, j = p*4 + m
    unsigned long long wr[50];
    #pragma unroll
    for (int jj = 0; jj < 50; jj++) {
        int j0 = 2*jj, j1 = 2*jj + 1;
        float2 f2;
        f2.x = w_proj[d*100 + (j0 & 3)*25 + (j0 >> 2)];
        f2.y = w_proj[d*100 + (j1 & 3)*25 + (j1 >> 2)];
        wr[jj] = *reinterpret_cast<unsigned long long*>(&f2);
    }
    const float gam = ln_gamma[d];
    const float bet = ln_beta[d];

    for (int gi = blockIdx.x; gi < NGROUP; gi += gridDim.x) {
        const int b  = gi / (L_ / G2);
        const int l0 = (gi % (L_ / G2)) * G2;

        __syncthreads();  // protect smem reuse across loop iterations
        if (tid < G2 * PATCH) {
            int g = tid / PATCH, p = tid % PATCH;
            float4 v = g_xs[(size_t)b * T_ + (size_t)(l0 + g) * PATCH + p];
            *reinterpret_cast<float4*>(&s[g][p*4]) = v;
        }
        __syncthreads();

        unsigned long long acc[G2];
        #pragma unroll
        for (int g = 0; g < G2; g++) acc[g] = 0ull;  // (0.0f, 0.0f)

        #pragma unroll
        for (int jj = 0; jj < 50; jj++) {
            #pragma unroll
            for (int g = 0; g < G2; g++) {
                unsigned long long sv =
                    *reinterpret_cast<const unsigned long long*>(&s[g][2*jj]);
                asm("fma.rn.f32x2 %0, %1, %2, %3;"
                    : "=l"(acc[g]) : "l"(wr[jj]), "l"(sv), "l"(acc[g]));
            }
        }

        float h0[G2], rsum[G2], rsq[G2];
        #pragma unroll
        for (int g = 0; g < G2; g++) {
            float2 a = *reinterpret_cast<float2*>(&acc[g]);
            h0[g]   = a.x + a.y;
            rsum[g] = h0[g];
            rsq[g]  = h0[g] * h0[g];
        }
        #pragma unroll
        for (int off = 16; off > 0; off >>= 1) {
            #pragma unroll
            for (int g = 0; g < G2; g++) {
                rsum[g] += __shfl_down_sync(0xffffffffu, rsum[g], off);
                rsq[g]  += __shfl_down_sync(0xffffffffu, rsq[g],  off);
            }
        }
        if (lane == 0) {
            #pragma unroll
            for (int g = 0; g < G2; g++) {
                red[warp][g]      = rsum[g];
                red[warp][G2 + g] = rsq[g];
            }
        }
        __syncthreads();
        if (tid < G2) {
            float ssum = 0.f, ssq = 0.f;
            #pragma unroll
            for (int w = 0; w < 5; w++) { ssum += red[w][tid]; ssq += red[w][G2 + tid]; }
            float mu  = ssum * (1.0f / 160.0f);
            float var = ssq * (1.0f / 160.0f) - mu * mu;
            stats[tid][0] = mu;
            stats[tid][1] = rsqrtf(var + 1e-5f);
        }
        __syncthreads();
        #pragma unroll
        for (int g = 0; g < G2; g++) {
            float h = (h0[g] - stats[g][0]) * stats[g][1] * gam + bet;
            out_h[((size_t)b * L_ + (l0 + g)) * D_ + d] = h;
        }
    }
}

// ---------------------------------------------------------------------------
extern "C" void kernel_launch(void* const* d_in, const int* in_sizes, int n_in,
                              void* d_out, int out_size) {
    const float* X           = (const float*)d_in[0];
    const float* M           = (const float*)d_in[1];
    const float* w_env       = (const float*)d_in[2];
    const float* w_burst     = (const float*)d_in[3];
    const float* synergy_raw = (const float*)d_in[4];
    const float* w_pre_dw    = (const float*)d_in[5];
    const float* w_pre_pw    = (const float*)d_in[6];
    const float* w_proj      = (const float*)d_in[7];
    const float* ln_gamma    = (const float*)d_in[8];
    const float* ln_beta     = (const float*)d_in[9];

    float* out_h  = (float*)d_out;
    float* out_mp = out_h + (size_t)B_ * L_ * D_;

    dim3 g1(T_ / TILE, B_);
    stage1_kernel<<<g1, NTHR1>>>((const float4*)X, (const float4*)M,
                                 w_env, w_burst, synergy_raw,
                                 w_pre_dw, w_pre_pw, out_mp);
    stage2_kernel<<<592, NTHR2>>>(w_proj, ln_gamma, ln_beta, out_h);
}

// round 4
// speedup vs baseline: 1.4660x; 1.4660x over previous
#include <cuda_runtime.h>
#include <math.h>

#define B_    64
#define T_    50000
#define MSYN  4
#define D_    160
#define PATCH 25
#define L_    2000
#define KENV  25
#define KBUR  9
#define KPRE  9

#define TILE  500
#define NTHR1 128

// ---- stage2 config ----
#define S2T    512            // threads (16 warps)
#define NR2    64             // rows per tile
#define NT2    2000           // 128000 / 64
#define APAD   112            // padded floats per A row (16B-aligned stride)
#define S2GRID 148
#define S2_SMEM_BYTES (16000*4 + 2*NR2*APAD*4)   // 64000 + 57344 = 121344

typedef unsigned long long u64;

// xs[b][t] float4 over the 4 synergy channels
__device__ float4 g_xs[(size_t)B_ * T_];

__device__ __forceinline__ u64 f2fma(u64 a, u64 b, u64 c) {
    u64 d; asm("fma.rn.f32x2 %0,%1,%2,%3;" : "=l"(d) : "l"(a), "l"(b), "l"(c)); return d;
}
__device__ __forceinline__ u64 f2add(u64 a, u64 b) {
    u64 d; asm("add.rn.f32x2 %0,%1,%2;" : "=l"(d) : "l"(a), "l"(b)); return d;
}
__device__ __forceinline__ u64 dup2(float x) {
    u64 r; asm("mov.b64 %0,{%1,%1};" : "=l"(r) : "f"(x)); return r;
}
__device__ __forceinline__ u64 pack2(float a, float b) {
    u64 r; asm("mov.b64 %0,{%1,%2};" : "=l"(r) : "f"(a), "f"(b)); return r;
}
__device__ __forceinline__ void unpack2(u64 v, float& lo, float& hi) {
    asm("mov.b64 {%0,%1},%2;" : "=f"(lo), "=f"(hi) : "l"(v));
}
__device__ __forceinline__ float softplusf_(float v) {
    return fmaxf(v, 0.0f) + log1pf(expf(-fabsf(v)));
}
__device__ __forceinline__ float gelu_exact(float v) { return v * normcdff(v); }

// ---------------------------------------------------------------------------
// Stage 1: fused front pipeline -> xs scratch + m_patch
// ---------------------------------------------------------------------------
__global__ __launch_bounds__(NTHR1) void stage1_kernel(
    const float4* __restrict__ X, const float4* __restrict__ M,
    const float*  __restrict__ w_env, const float* __restrict__ w_burst,
    const float*  __restrict__ synergy_raw, const float* __restrict__ w_pre_dw,
    const float*  __restrict__ w_pre_pw, float* __restrict__ out_mpatch)
{
    __shared__ float4 sx  [TILE + 32];   // x = X*M,  t = t0-16+j
    __shared__ float4 sabs[TILE + 32];   // |x|
    __shared__ float4 sdx [TILE + 16];   // |dx|,     t = t0-8+i
    __shared__ float4 sS0 [TILE + 8];    // S0,       t = t0-4+i
    __shared__ unsigned smask[TILE];
    __shared__ float  smt[TILE];
    __shared__ float4 swe[KENV], swb[KBUR], swd[KPRE];
    __shared__ float4 slut[16];
    __shared__ float  slmt[16];

    const int tid  = threadIdx.x;
    const int tile = blockIdx.x;
    const int b    = blockIdx.y;
    const int t0   = tile * TILE;

    // normalized synergy matrix (regs, every thread)
    float Wm[4][4];
    #pragma unroll
    for (int m = 0; m < 4; m++) {
        float r0 = softplusf_(synergy_raw[m*4+0]);
        float r1 = softplusf_(synergy_raw[m*4+1]);
        float r2 = softplusf_(synergy_raw[m*4+2]);
        float r3 = softplusf_(synergy_raw[m*4+3]);
        float inv = 1.0f / fmaxf(r0+r1+r2+r3, 1e-6f);
        Wm[m][0]=r0*inv; Wm[m][1]=r1*inv; Wm[m][2]=r2*inv; Wm[m][3]=r3*inv;
    }
    // packed pairs for mixes
    u64 Wp01[4], Wp23[4], pw01[4], pw23[4];
    #pragma unroll
    for (int c = 0; c < 4; c++) {
        Wp01[c] = pack2(Wm[0][c], Wm[1][c]);
        Wp23[c] = pack2(Wm[2][c], Wm[3][c]);
        pw01[c] = pack2(w_pre_pw[0*4+c], w_pre_pw[1*4+c]);
        pw23[c] = pack2(w_pre_pw[2*4+c], w_pre_pw[3*4+c]);
    }

    if (tid < KENV) swe[tid] = make_float4(0.9f*w_env[tid], 0.9f*w_env[25+tid],
                                           0.9f*w_env[50+tid], 0.9f*w_env[75+tid]);
    if (tid < KBUR) swb[tid] = make_float4(0.6f*w_burst[tid], 0.6f*w_burst[9+tid],
                                           0.6f*w_burst[18+tid], 0.6f*w_burst[27+tid]);
    if (tid < KPRE) swd[tid] = make_float4(w_pre_dw[tid], w_pre_dw[9+tid],
                                           w_pre_dw[18+tid], w_pre_dw[27+tid]);
    if (tid < 16) {
        float mm[4]; float4 sv; float s = 0.f;
        #pragma unroll
        for (int c = 0; c < 4; c++) mm[c] = (float)((tid >> c) & 1);
        float v0 = Wm[0][0]*mm[0]+Wm[0][1]*mm[1]+Wm[0][2]*mm[2]+Wm[0][3]*mm[3];
        float v1 = Wm[1][0]*mm[0]+Wm[1][1]*mm[1]+Wm[1][2]*mm[2]+Wm[1][3]*mm[3];
        float v2 = Wm[2][0]*mm[0]+Wm[2][1]*mm[1]+Wm[2][2]*mm[2]+Wm[2][3]*mm[3];
        float v3 = Wm[3][0]*mm[0]+Wm[3][1]*mm[1]+Wm[3][2]*mm[2]+Wm[3][3]*mm[3];
        sv.x = fminf(fmaxf(v0,0.f),1.f); sv.y = fminf(fmaxf(v1,0.f),1.f);
        sv.z = fminf(fmaxf(v2,0.f),1.f); sv.w = fminf(fmaxf(v3,0.f),1.f);
        s = sv.x + sv.y + sv.z + sv.w;
        slut[tid] = sv; slmt[tid] = (s > 0.f) ? 1.f : 0.f;
    }

    // Phase A: x = X*M, |x|, mask bits
    const float4* Xb = X + (size_t)b * T_;
    const float4* Mb = M + (size_t)b * T_;
    for (int j = tid; j < TILE + 32; j += NTHR1) {
        int t = t0 - 16 + j;
        float4 xv = make_float4(0.f,0.f,0.f,0.f);
        float4 av = make_float4(0.f,0.f,0.f,0.f);
        if (t >= 0 && t < T_) {
            float4 X4 = Xb[t], M4 = Mb[t];
            xv.x = X4.x*M4.x; xv.y = X4.y*M4.y; xv.z = X4.z*M4.z; xv.w = X4.w*M4.w;
            av.x = fabsf(xv.x); av.y = fabsf(xv.y); av.z = fabsf(xv.z); av.w = fabsf(xv.w);
            if (j >= 16 && j < 16 + TILE) {
                unsigned mk = (M4.x > 0.f ? 1u : 0u) | (M4.y > 0.f ? 2u : 0u)
                            | (M4.z > 0.f ? 4u : 0u) | (M4.w > 0.f ? 8u : 0u);
                smask[j - 16] = mk;
            }
        }
        sx[j] = xv; sabs[j] = av;
    }
    __syncthreads();

    // Phase dx
    for (int i = tid; i < TILE + 16; i += NTHR1) {
        int t = t0 - 8 + i;
        float4 v = make_float4(0.f,0.f,0.f,0.f);
        if (t >= 1 && t < T_) {
            float4 a = sx[i+8], c = sx[i+7];
            v.x = fabsf(a.x-c.x); v.y = fabsf(a.y-c.y);
            v.z = fabsf(a.z-c.z); v.w = fabsf(a.w-c.w);
        }
        sdx[i] = v;
    }
    __syncthreads();

    // Phase B: env + burst + mix -> S0 (f32x2)
    {
        const u64* sabs64 = (const u64*)sabs;
        const u64* sdx64  = (const u64*)sdx;
        const u64* sx64   = (const u64*)sx;
        const u64* swe64  = (const u64*)swe;
        const u64* swb64  = (const u64*)swb;
        const u64 c02 = pack2(0.2f, 0.2f);
        for (int i = tid; i < TILE + 8; i += NTHR1) {
            int t = t0 - 4 + i;
            float4 out = make_float4(0.f,0.f,0.f,0.f);
            if (t >= 0 && t < T_) {
                u64 e01 = 0ull, e23 = 0ull;
                #pragma unroll
                for (int k = 0; k < KENV; k++) {
                    e01 = f2fma(sabs64[2*(i+k)],   swe64[2*k],   e01);
                    e23 = f2fma(sabs64[2*(i+k)+1], swe64[2*k+1], e23);
                }
                u64 b01 = 0ull, b23 = 0ull;
                #pragma unroll
                for (int k = 0; k < KBUR; k++) {
                    b01 = f2fma(sdx64[2*(i+k)],   swb64[2*k],   b01);
                    b23 = f2fma(sdx64[2*(i+k)+1], swb64[2*k+1], b23);
                }
                u64 xm01 = f2fma(sx64[2*(i+12)],   c02, f2add(e01, b01));
                u64 xm23 = f2fma(sx64[2*(i+12)+1], c02, f2add(e23, b23));
                float m0,m1,m2,m3;
                unpack2(xm01, m0, m1); unpack2(xm23, m2, m3);
                u64 d0 = dup2(m0), d1 = dup2(m1), d2 = dup2(m2), d3 = dup2(m3);
                u64 s01 = 0ull, s23 = 0ull;
                s01 = f2fma(d0, Wp01[0], s01); s01 = f2fma(d1, Wp01[1], s01);
                s01 = f2fma(d2, Wp01[2], s01); s01 = f2fma(d3, Wp01[3], s01);
                s23 = f2fma(d0, Wp23[0], s23); s23 = f2fma(d1, Wp23[1], s23);
                s23 = f2fma(d2, Wp23[2], s23); s23 = f2fma(d3, Wp23[3], s23);
                unpack2(s01, out.x, out.y); unpack2(s23, out.z, out.w);
            }
            sS0[i] = out;
        }
    }
    __syncthreads();

    // Phase C: dwconv K=9 + gelu, pointwise + gelu, xs, m_time
    {
        const u64* sS064 = (const u64*)sS0;
        const u64* swd64 = (const u64*)swd;
        for (int i = tid; i < TILE; i += NTHR1) {
            u64 a01 = 0ull, a23 = 0ull;
            #pragma unroll
            for (int k = 0; k < KPRE; k++) {
                a01 = f2fma(sS064[2*(i+k)],   swd64[2*k],   a01);
                a23 = f2fma(sS064[2*(i+k)+1], swd64[2*k+1], a23);
            }
            float g0,g1,g2,g3;
            unpack2(a01, g0, g1); unpack2(a23, g2, g3);
            float s1_0 = gelu_exact(g0), s1_1 = gelu_exact(g1);
            float s1_2 = gelu_exact(g2), s1_3 = gelu_exact(g3);

            u64 t01 = 0ull, t23 = 0ull;
            u64 e0 = dup2(s1_0), e1 = dup2(s1_1), e2 = dup2(s1_2), e3 = dup2(s1_3);
            t01 = f2fma(e0, pw01[0], t01); t01 = f2fma(e1, pw01[1], t01);
            t01 = f2fma(e2, pw01[2], t01); t01 = f2fma(e3, pw01[3], t01);
            t23 = f2fma(e0, pw23[0], t23); t23 = f2fma(e1, pw23[1], t23);
            t23 = f2fma(e2, pw23[2], t23); t23 = f2fma(e3, pw23[3], t23);
            float v0,v1,v2,v3;
            unpack2(t01, v0, v1); unpack2(t23, v2, v3);

            unsigned mk = smask[i];
            float4 smv = slut[mk];
            float4 xs;
            xs.x = gelu_exact(v0) * smv.x;
            xs.y = gelu_exact(v1) * smv.y;
            xs.z = gelu_exact(v2) * smv.z;
            xs.w = gelu_exact(v3) * smv.w;
            g_xs[(size_t)b * T_ + t0 + i] = xs;
            smt[i] = slmt[mk];
        }
    }
    __syncthreads();

    // m_patch: 20 patches per tile
    if (tid < TILE / PATCH) {
        float s = 0.f;
        int base = tid * PATCH;
        #pragma unroll
        for (int p = 0; p < PATCH; p++) s += smt[base + p];
        out_mpatch[b * L_ + tile * (TILE/PATCH) + tid] =
            (s * (1.0f/25.0f) > 0.1f) ? 1.0f : 0.0f;
    }
}

// ---------------------------------------------------------------------------
// Stage 2: [128000 x 100] x [100 x 160] + LayerNorm(160)
// persistent register-tiled GEMM, W in smem (f32x2 over k-pairs), A double-buffered
// ---------------------------------------------------------------------------
__global__ __launch_bounds__(S2T, 1) void stage2_kernel(
    const float* __restrict__ w_proj, const float* __restrict__ ln_gamma,
    const float* __restrict__ ln_beta, float* __restrict__ out_h)
{
    extern __shared__ float sm2[];
    float* sW = sm2;               // 8000 float2: sW2[kk*160 + d] = (W[2kk][d], W[2kk+1][d])
    float* sA = sm2 + 16000;       // 2 buffers of [64][APAD]

    const int tid = threadIdx.x;
    const int tx  = tid & 31;
    const int ty  = tid >> 5;

    // Load W into smem, k-pair-packed, d-contiguous. k = 4p+m maps A float index.
    for (int i = tid; i < 8000; i += S2T) {
        int kk = i / 160, d = i - kk*160;
        int k0 = 2*kk, k1 = 2*kk + 1;
        float2 w;
        w.x = w_proj[d*100 + (k0 & 3)*25 + (k0 >> 2)];
        w.y = w_proj[d*100 + (k1 & 3)*25 + (k1 >> 2)];
        *(float2*)&sW[2*i] = w;
    }
    float gam[5], bet[5];
    #pragma unroll
    for (int c = 0; c < 5; c++) { gam[c] = ln_gamma[tx + 32*c]; bet[c] = ln_beta[tx + 32*c]; }

    float4 ld[4];
    int tt = blockIdx.x;
    if (tt < NT2) {
        #pragma unroll
        for (int it = 0; it < 4; it++) {
            int idx = tid + it*S2T;
            if (idx < NR2*25) {
                int r = idx / 25, p = idx - r*25;
                int rg = tt*NR2 + r;
                ld[it] = g_xs[(size_t)(rg / L_) * T_ + (rg % L_) * 25 + p];
            }
        }
    }

    int cur = 0;
    for (; tt < NT2; tt += S2GRID) {
        // commit prefetched tile tt into buffer cur
        {
            float* dst = sA + cur * (NR2*APAD);
            #pragma unroll
            for (int it = 0; it < 4; it++) {
                int idx = tid + it*S2T;
                if (idx < NR2*25) {
                    int r = idx / 25, p = idx - r*25;
                    *(float4*)&dst[r*APAD + 4*p] = ld[it];
                }
            }
        }
        // prefetch next tile into regs (overlaps with compute below)
        int nt = tt + S2GRID;
        if (nt < NT2) {
            #pragma unroll
            for (int it = 0; it < 4; it++) {
                int idx = tid + it*S2T;
                if (idx < NR2*25) {
                    int r = idx / 25, p = idx - r*25;
                    int rg = nt*NR2 + r;
                    ld[it] = g_xs[(size_t)(rg / L_) * T_ + (rg % L_) * 25 + p];
                }
            }
        }
        __syncthreads();

        // compute 4 rows x 160 cols per thread-row-group
        u64 acc[4][5];
        #pragma unroll
        for (int rr = 0; rr < 4; rr++)
            #pragma unroll
            for (int c = 0; c < 5; c++) acc[rr][c] = 0ull;

        const u64* a0 = (const u64*)(sA + cur*(NR2*APAD) + (ty*4 + 0)*APAD);
        const u64* a1 = (const u64*)(sA + cur*(NR2*APAD) + (ty*4 + 1)*APAD);
        const u64* a2 = (const u64*)(sA + cur*(NR2*APAD) + (ty*4 + 2)*APAD);
        const u64* a3 = (const u64*)(sA + cur*(NR2*APAD) + (ty*4 + 3)*APAD);
        const u64* wrow = (const u64*)sW;

        #pragma unroll 5
        for (int kk = 0; kk < 50; kk++) {
            u64 wv[5];
            #pragma unroll
            for (int c = 0; c < 5; c++) wv[c] = wrow[kk*160 + tx + 32*c];
            u64 av0 = a0[kk], av1 = a1[kk], av2 = a2[kk], av3 = a3[kk];
            #pragma unroll
            for (int c = 0; c < 5; c++) {
                acc[0][c] = f2fma(av0, wv[c], acc[0][c]);
                acc[1][c] = f2fma(av1, wv[c], acc[1][c]);
                acc[2][c] = f2fma(av2, wv[c], acc[2][c]);
                acc[3][c] = f2fma(av3, wv[c], acc[3][c]);
            }
        }

        // epilogue: per-row LayerNorm over 160 (one warp owns each row)
        #pragma unroll
        for (int rr = 0; rr < 4; rr++) {
            float h[5]; float s = 0.f, q = 0.f;
            #pragma unroll
            for (int c = 0; c < 5; c++) {
                float lo, hi; unpack2(acc[rr][c], lo, hi);
                h[c] = lo + hi;
                s += h[c]; q += h[c]*h[c];
            }
            #pragma unroll
            for (int off = 16; off > 0; off >>= 1) {
                s += __shfl_xor_sync(0xffffffffu, s, off);
                q += __shfl_xor_sync(0xffffffffu, q, off);
            }
            float mu = s * (1.0f/160.0f);
            float rs = rsqrtf(q * (1.0f/160.0f) - mu*mu + 1e-5f);
            int rg = tt*NR2 + ty*4 + rr;
            float* o = out_h + (size_t)rg * D_ + tx;
            #pragma unroll
            for (int c = 0; c < 5; c++)
                o[32*c] = (h[c] - mu) * rs * gam[c] + bet[c];
        }
        __syncthreads();
        cur ^= 1;
    }
}

// ---------------------------------------------------------------------------
extern "C" void kernel_launch(void* const* d_in, const int* in_sizes, int n_in,
                              void* d_out, int out_size) {
    const float* X           = (const float*)d_in[0];
    const float* M           = (const float*)d_in[1];
    const float* w_env       = (const float*)d_in[2];
    const float* w_burst     = (const float*)d_in[3];
    const float* synergy_raw = (const float*)d_in[4];
    const float* w_pre_dw    = (const float*)d_in[5];
    const float* w_pre_pw    = (const float*)d_in[6];
    const float* w_proj      = (const float*)d_in[7];
    const float* ln_gamma    = (const float*)d_in[8];
    const float* ln_beta     = (const float*)d_in[9];

    float* out_h  = (float*)d_out;
    float* out_mp = out_h + (size_t)B_ * L_ * D_;

    static int attr_done = 0;
    if (!attr_done) {
        cudaFuncSetAttribute(stage2_kernel,
                             cudaFuncAttributeMaxDynamicSharedMemorySize,
                             S2_SMEM_BYTES);
        attr_done = 1;
    }

    dim3 g1(T_ / TILE, B_);
    stage1_kernel<<<g1, NTHR1>>>((const float4*)X, (const float4*)M,
                                 w_env, w_burst, synergy_raw,
                                 w_pre_dw, w_pre_pw, out_mp);
    stage2_kernel<<<S2GRID, S2T, S2_SMEM_BYTES>>>(w_proj, ln_gamma, ln_beta, out_h);
}

// round 9
// speedup vs baseline: 1.6891x; 1.1522x over previous
#include <cuda_runtime.h>
#include <cstdint>
#include <stdint.h>
#include <math.h>

#define B_    64
#define T_    50000
#define D_    160
#define PATCH 25
#define L_    2000
#define KENV  25
#define KBUR  9
#define KPRE  9

#define TILE  500
#define NTHR1 128

// ---- stage2 config ----
#define S2T     512
#define NR2     128               // rows per tile
#define NT2     1000              // 128000 / 128
#define AROW    100               // floats per A row
#define S2GRID  148
#define S2ABUF  (NR2*AROW)        // 12800 floats per buffer
#define S2_SMEM_BYTES (16000*4 + 2*S2ABUF*4)   // 64000 + 102400 = 166400

typedef unsigned long long u64;
typedef unsigned int u32;

// xs[b][t] float4 over the 4 synergy channels; flat patch index rg -> rg*25+p
__device__ float4 g_xs[(size_t)B_ * T_];

__device__ __forceinline__ u64 f2fma(u64 a, u64 b, u64 c) {
    u64 d; asm("fma.rn.f32x2 %0,%1,%2,%3;" : "=l"(d) : "l"(a), "l"(b), "l"(c)); return d;
}
__device__ __forceinline__ u64 f2add(u64 a, u64 b) {
    u64 d; asm("add.rn.f32x2 %0,%1,%2;" : "=l"(d) : "l"(a), "l"(b)); return d;
}
__device__ __forceinline__ u64 dup2(float x) {
    u64 r; asm("mov.b64 %0,{%1,%1};" : "=l"(r) : "f"(x)); return r;
}
__device__ __forceinline__ u64 pack2(float a, float b) {
    u64 r; asm("mov.b64 %0,{%1,%2};" : "=l"(r) : "f"(a), "f"(b)); return r;
}
__device__ __forceinline__ void unpack2(u64 v, float& lo, float& hi) {
    asm("mov.b64 {%0,%1},%2;" : "=f"(lo), "=f"(hi) : "l"(v));
}
__device__ __forceinline__ float softplusf_(float v) {
    return fmaxf(v, 0.0f) + log1pf(expf(-fabsf(v)));
}
__device__ __forceinline__ float gelu_exact(float v) { return v * normcdff(v); }

__device__ __forceinline__ void cpasync16(u32 dst, const void* src) {
    asm volatile("cp.async.cg.shared.global [%0], [%1], 16;" :: "r"(dst), "l"(src));
}
#define CP_COMMIT() asm volatile("cp.async.commit_group;")
#define CP_WAIT1()  asm volatile("cp.async.wait_group 1;")

// ---------------------------------------------------------------------------
// Stage 1: fused front pipeline -> xs scratch + m_patch
// Each thread computes 4 consecutive points with sliding register windows.
// ---------------------------------------------------------------------------
__global__ __launch_bounds__(NTHR1) void stage1_kernel(
    const float4* __restrict__ X, const float4* __restrict__ M,
    const float*  __restrict__ w_env, const float* __restrict__ w_burst,
    const float*  __restrict__ synergy_raw, const float* __restrict__ w_pre_dw,
    const float*  __restrict__ w_pre_pw, float* __restrict__ out_mpatch)
{
    __shared__ float4 sx  [TILE + 32];   // x = X*M,  t = t0-16+j
    __shared__ float4 sabs[TILE + 32];   // |x|
    __shared__ float4 sdx [TILE + 16];   // |dx|,     t = t0-8+i
    __shared__ float4 sS0 [TILE + 8];    // S0,       t = t0-4+i
    __shared__ unsigned smask[TILE];
    __shared__ float  smt[TILE];
    __shared__ float4 swe[KENV], swb[KBUR], swd[KPRE];
    __shared__ float4 slut[16];
    __shared__ float  slmt[16];

    const int tid  = threadIdx.x;
    const int tile = blockIdx.x;
    const int b    = blockIdx.y;
    const int t0   = tile * TILE;

    // normalized synergy matrix
    float Wm[4][4];
    #pragma unroll
    for (int m = 0; m < 4; m++) {
        float r0 = softplusf_(synergy_raw[m*4+0]);
        float r1 = softplusf_(synergy_raw[m*4+1]);
        float r2 = softplusf_(synergy_raw[m*4+2]);
        float r3 = softplusf_(synergy_raw[m*4+3]);
        float inv = 1.0f / fmaxf(r0+r1+r2+r3, 1e-6f);
        Wm[m][0]=r0*inv; Wm[m][1]=r1*inv; Wm[m][2]=r2*inv; Wm[m][3]=r3*inv;
    }
    u64 Wp01[4], Wp23[4], pw01[4], pw23[4];
    #pragma unroll
    for (int c = 0; c < 4; c++) {
        Wp01[c] = pack2(Wm[0][c], Wm[1][c]);
        Wp23[c] = pack2(Wm[2][c], Wm[3][c]);
        pw01[c] = pack2(w_pre_pw[0*4+c], w_pre_pw[1*4+c]);
        pw23[c] = pack2(w_pre_pw[2*4+c], w_pre_pw[3*4+c]);
    }

    if (tid < KENV) swe[tid] = make_float4(0.9f*w_env[tid], 0.9f*w_env[25+tid],
                                           0.9f*w_env[50+tid], 0.9f*w_env[75+tid]);
    if (tid < KBUR) swb[tid] = make_float4(0.6f*w_burst[tid], 0.6f*w_burst[9+tid],
                                           0.6f*w_burst[18+tid], 0.6f*w_burst[27+tid]);
    if (tid < KPRE) swd[tid] = make_float4(w_pre_dw[tid], w_pre_dw[9+tid],
                                           w_pre_dw[18+tid], w_pre_dw[27+tid]);
    if (tid < 16) {
        float mm[4]; float4 sv;
        #pragma unroll
        for (int c = 0; c < 4; c++) mm[c] = (float)((tid >> c) & 1);
        float v0 = Wm[0][0]*mm[0]+Wm[0][1]*mm[1]+Wm[0][2]*mm[2]+Wm[0][3]*mm[3];
        float v1 = Wm[1][0]*mm[0]+Wm[1][1]*mm[1]+Wm[1][2]*mm[2]+Wm[1][3]*mm[3];
        float v2 = Wm[2][0]*mm[0]+Wm[2][1]*mm[1]+Wm[2][2]*mm[2]+Wm[2][3]*mm[3];
        float v3 = Wm[3][0]*mm[0]+Wm[3][1]*mm[1]+Wm[3][2]*mm[2]+Wm[3][3]*mm[3];
        sv.x = fminf(fmaxf(v0,0.f),1.f); sv.y = fminf(fmaxf(v1,0.f),1.f);
        sv.z = fminf(fmaxf(v2,0.f),1.f); sv.w = fminf(fmaxf(v3,0.f),1.f);
        slut[tid] = sv;
        slmt[tid] = ((sv.x+sv.y+sv.z+sv.w) > 0.f) ? 1.f : 0.f;
    }

    // Phase A: x = X*M, |x|, mask bits
    const float4* Xb = X + (size_t)b * T_;
    const float4* Mb = M + (size_t)b * T_;
    for (int j = tid; j < TILE + 32; j += NTHR1) {
        int t = t0 - 16 + j;
        float4 xv = make_float4(0.f,0.f,0.f,0.f);
        float4 av = make_float4(0.f,0.f,0.f,0.f);
        if (t >= 0 && t < T_) {
            float4 X4 = Xb[t], M4 = Mb[t];
            xv.x = X4.x*M4.x; xv.y = X4.y*M4.y; xv.z = X4.z*M4.z; xv.w = X4.w*M4.w;
            av.x = fabsf(xv.x); av.y = fabsf(xv.y); av.z = fabsf(xv.z); av.w = fabsf(xv.w);
            if (j >= 16 && j < 16 + TILE) {
                unsigned mk = (M4.x > 0.f ? 1u : 0u) | (M4.y > 0.f ? 2u : 0u)
                            | (M4.z > 0.f ? 4u : 0u) | (M4.w > 0.f ? 8u : 0u);
                smask[j - 16] = mk;
            }
        }
        sx[j] = xv; sabs[j] = av;
    }
    __syncthreads();

    // Phase dx
    for (int i = tid; i < TILE + 16; i += NTHR1) {
        int t = t0 - 8 + i;
        float4 v = make_float4(0.f,0.f,0.f,0.f);
        if (t >= 1 && t < T_) {
            float4 a = sx[i+8], c = sx[i+7];
            v.x = fabsf(a.x-c.x); v.y = fabsf(a.y-c.y);
            v.z = fabsf(a.z-c.z); v.w = fabsf(a.w-c.w);
        }
        sdx[i] = v;
    }
    __syncthreads();

    const u64* sabs64 = (const u64*)sabs;
    const u64* sdx64  = (const u64*)sdx;
    const u64* sx64   = (const u64*)sx;
    const u64* swe64  = (const u64*)swe;
    const u64* swb64  = (const u64*)swb;
    const u64* sS064  = (const u64*)sS0;
    const u64  c02    = pack2(0.2f, 0.2f);

    // Phase B: env (25) + burst (9) + 0.2x, synergy mix -> sS0. 4 points/thread.
    if (tid < 127) {
        const int i0 = 4 * tid;
        u64 xm[2][4];
        #pragma unroll
        for (int pp = 0; pp < 2; pp++) {
            u64 e0=0,e1=0,e2=0,e3=0;
            u64 d0 = sabs64[2*i0+pp], d1 = sabs64[2*(i0+1)+pp], d2 = sabs64[2*(i0+2)+pp];
            #pragma unroll
            for (int k = 0; k < KENV; k++) {
                u64 w  = swe64[2*k+pp];
                u64 d3 = sabs64[2*(i0+3+k)+pp];
                e0 = f2fma(d0,w,e0); e1 = f2fma(d1,w,e1);
                e2 = f2fma(d2,w,e2); e3 = f2fma(d3,w,e3);
                d0 = d1; d1 = d2; d2 = d3;
            }
            u64 u0=0,u1=0,u2=0,u3=0;
            d0 = sdx64[2*i0+pp]; d1 = sdx64[2*(i0+1)+pp]; d2 = sdx64[2*(i0+2)+pp];
            #pragma unroll
            for (int k = 0; k < KBUR; k++) {
                u64 w  = swb64[2*k+pp];
                u64 d3 = sdx64[2*(i0+3+k)+pp];
                u0 = f2fma(d0,w,u0); u1 = f2fma(d1,w,u1);
                u2 = f2fma(d2,w,u2); u3 = f2fma(d3,w,u3);
                d0 = d1; d1 = d2; d2 = d3;
            }
            xm[pp][0] = f2fma(sx64[2*(i0+12)+pp], c02, f2add(e0,u0));
            xm[pp][1] = f2fma(sx64[2*(i0+13)+pp], c02, f2add(e1,u1));
            xm[pp][2] = f2fma(sx64[2*(i0+14)+pp], c02, f2add(e2,u2));
            xm[pp][3] = f2fma(sx64[2*(i0+15)+pp], c02, f2add(e3,u3));
        }
        #pragma unroll
        for (int r = 0; r < 4; r++) {
            float m0,m1,m2,m3;
            unpack2(xm[0][r], m0, m1); unpack2(xm[1][r], m2, m3);
            u64 dd0 = dup2(m0), dd1 = dup2(m1), dd2 = dup2(m2), dd3 = dup2(m3);
            u64 s01 = 0ull, s23 = 0ull;
            s01 = f2fma(dd0, Wp01[0], s01); s01 = f2fma(dd1, Wp01[1], s01);
            s01 = f2fma(dd2, Wp01[2], s01); s01 = f2fma(dd3, Wp01[3], s01);
            s23 = f2fma(dd0, Wp23[0], s23); s23 = f2fma(dd1, Wp23[1], s23);
            s23 = f2fma(dd2, Wp23[2], s23); s23 = f2fma(dd3, Wp23[3], s23);
            float4 o;
            unpack2(s01, o.x, o.y); unpack2(s23, o.z, o.w);
            int tb = t0 - 4 + i0 + r;
            if (tb < 0 || tb >= T_) o = make_float4(0.f,0.f,0.f,0.f);
            sS0[i0 + r] = o;
        }
    }
    __syncthreads();

    // Phase C: dwconv K=9 + gelu, pointwise + gelu, mask, xs, m_time. 4 pts/thread.
    if (tid < 125) {
        const int i0 = 4 * tid;
        u64 aa[2][4];
        #pragma unroll
        for (int pp = 0; pp < 2; pp++) {
            u64 a0=0,a1=0,a2=0,a3=0;
            u64 d0 = sS064[2*i0+pp], d1 = sS064[2*(i0+1)+pp], d2 = sS064[2*(i0+2)+pp];
            #pragma unroll
            for (int k = 0; k < KPRE; k++) {
                u64 w  = ((const u64*)swd)[2*k+pp];
                u64 d3 = sS064[2*(i0+3+k)+pp];
                a0 = f2fma(d0,w,a0); a1 = f2fma(d1,w,a1);
                a2 = f2fma(d2,w,a2); a3 = f2fma(d3,w,a3);
                d0 = d1; d1 = d2; d2 = d3;
            }
            aa[pp][0]=a0; aa[pp][1]=a1; aa[pp][2]=a2; aa[pp][3]=a3;
        }
        #pragma unroll
        for (int r = 0; r < 4; r++) {
            float g0,g1,g2,g3;
            unpack2(aa[0][r], g0, g1); unpack2(aa[1][r], g2, g3);
            float s1_0 = gelu_exact(g0), s1_1 = gelu_exact(g1);
            float s1_2 = gelu_exact(g2), s1_3 = gelu_exact(g3);

            u64 t01 = 0ull, t23 = 0ull;
            u64 e0 = dup2(s1_0), e1 = dup2(s1_1), e2 = dup2(s1_2), e3 = dup2(s1_3);
            t01 = f2fma(e0, pw01[0], t01); t01 = f2fma(e1, pw01[1], t01);
            t01 = f2fma(e2, pw01[2], t01); t01 = f2fma(e3, pw01[3], t01);
            t23 = f2fma(e0, pw23[0], t23); t23 = f2fma(e1, pw23[1], t23);
            t23 = f2fma(e2, pw23[2], t23); t23 = f2fma(e3, pw23[3], t23);
            float v0,v1,v2,v3;
            unpack2(t01, v0, v1); unpack2(t23, v2, v3);

            unsigned mk = smask[i0 + r];
            float4 smv = slut[mk];
            float4 xs;
            xs.x = gelu_exact(v0) * smv.x;
            xs.y = gelu_exact(v1) * smv.y;
            xs.z = gelu_exact(v2) * smv.z;
            xs.w = gelu_exact(v3) * smv.w;
            g_xs[(size_t)b * T_ + t0 + i0 + r] = xs;
            smt[i0 + r] = slmt[mk];
        }
    }
    __syncthreads();

    // m_patch: 20 patches per tile
    if (tid < TILE / PATCH) {
        float s = 0.f;
        int base = tid * PATCH;
        #pragma unroll
        for (int p = 0; p < PATCH; p++) s += smt[base + p];
        out_mpatch[b * L_ + tile * (TILE/PATCH) + tid] =
            (s * (1.0f/25.0f) > 0.1f) ? 1.0f : 0.0f;
    }
}

// ---------------------------------------------------------------------------
// Stage 2: [128000 x 100] x [100 x 160] + LayerNorm(160)
// persistent GEMM: 16 warps x 8 rows, W smem-resident, A via cp.async dbuf
// ---------------------------------------------------------------------------
__global__ __launch_bounds__(S2T, 1) void stage2_kernel(
    const float* __restrict__ w_proj, const float* __restrict__ ln_gamma,
    const float* __restrict__ ln_beta, float* __restrict__ out_h)
{
    extern __shared__ float sm2[];
    float* sW = sm2;               // [kk][d] float2: (W[2kk][d], W[2kk+1][d])
    float* sA = sm2 + 16000;       // 2 buffers of [128][100]

    const int tid = threadIdx.x;
    const int tx  = tid & 31;
    const int ty  = tid >> 5;

    // W into smem, k-pair-packed, d-contiguous. A float index k = 4p+m.
    for (int i = tid; i < 8000; i += S2T) {
        int kk = i / 160, d = i - kk*160;
        int k0 = 2*kk, k1 = 2*kk + 1;
        float2 w;
        w.x = w_proj[d*100 + (k0 & 3)*25 + (k0 >> 2)];
        w.y = w_proj[d*100 + (k1 & 3)*25 + (k1 >> 2)];
        *(float2*)&sW[2*i] = w;
    }
    float gam[5], bet[5];
    #pragma unroll
    for (int c = 0; c < 5; c++) { gam[c] = ln_gamma[tx + 32*c]; bet[c] = ln_beta[tx + 32*c]; }

    const float4* gxs = (const float4*)g_xs;   // flat: patch rg -> [rg*25 .. +25)
    u32 sA_u32;
    { void* p = sA; asm("{ .reg .u64 t; cvta.to.shared.u64 t, %1; cvt.u32.u64 %0, t; }"
                        : "=r"(sA_u32) : "l"(p)); }

    // prologue: tile blockIdx.x into buffer 0
    {
        int base = blockIdx.x * (NR2*25);
        #pragma unroll
        for (int it = 0; it < 7; it++) {
            int i = tid + it * S2T;
            if (i < NR2*25) {
                int r = i / 25, p = i - r*25;
                cpasync16(sA_u32 + (r*AROW + 4*p)*4, gxs + base + i);
            }
        }
        CP_COMMIT();
    }

    int cur = 0;
    for (int tt = blockIdx.x; tt < NT2; tt += S2GRID) {
        int nt = tt + S2GRID;
        if (nt < NT2) {
            int base = nt * (NR2*25);
            u32 dst = sA_u32 + (u32)(cur^1) * (S2ABUF*4);
            #pragma unroll
            for (int it = 0; it < 7; it++) {
                int i = tid + it * S2T;
                if (i < NR2*25) {
                    int r = i / 25, p = i - r*25;
                    cpasync16(dst + (r*AROW + 4*p)*4, gxs + base + i);
                }
            }
        }
        CP_COMMIT();
        CP_WAIT1();
        __syncthreads();

        // compute: 8 rows x 160 cols per warp
        u64 acc[8][5];
        #pragma unroll
        for (int r = 0; r < 8; r++)
            #pragma unroll
            for (int c = 0; c < 5; c++) acc[r][c] = 0ull;

        const float* aT = sA + cur * S2ABUF + (ty*8) * AROW;
        const u64*   wp = (const u64*)sW;

        #pragma unroll 10
        for (int kk = 0; kk < 50; kk++) {
            u64 wv[5];
            #pragma unroll
            for (int c = 0; c < 5; c++) wv[c] = wp[kk*160 + tx + 32*c];
            #pragma unroll
            for (int r = 0; r < 8; r++) {
                u64 av = *(const u64*)(aT + r*AROW + 2*kk);
                #pragma unroll
                for (int c = 0; c < 5; c++) acc[r][c] = f2fma(av, wv[c], acc[r][c]);
            }
        }

        // epilogue: LayerNorm over 160 per row (warp-wide shfl reduce)
        #pragma unroll
        for (int r = 0; r < 8; r++) {
            float h[5]; float s = 0.f, q = 0.f;
            #pragma unroll
            for (int c = 0; c < 5; c++) {
                float lo, hi; unpack2(acc[r][c], lo, hi);
                h[c] = lo + hi;
                s += h[c]; q += h[c]*h[c];
            }
            #pragma unroll
            for (int off = 16; off > 0; off >>= 1) {
                s += __shfl_xor_sync(0xffffffffu, s, off);
                q += __shfl_xor_sync(0xffffffffu, q, off);
            }
            float mu = s * (1.0f/160.0f);
            float rs = rsqrtf(q * (1.0f/160.0f) - mu*mu + 1e-5f);
            int rg = tt*NR2 + ty*8 + r;
            float* o = out_h + (size_t)rg * D_ + tx;
            #pragma unroll
            for (int c = 0; c < 5; c++)
                o[32*c] = (h[c] - mu) * rs * gam[c] + bet[c];
        }
        __syncthreads();
        cur ^= 1;
    }
}

// ---------------------------------------------------------------------------
extern "C" void kernel_launch(void* const* d_in, const int* in_sizes, int n_in,
                              void* d_out, int out_size) {
    const float* X           = (const float*)d_in[0];
    const float* M           = (const float*)d_in[1];
    const float* w_env       = (const float*)d_in[2];
    const float* w_burst     = (const float*)d_in[3];
    const float* synergy_raw = (const float*)d_in[4];
    const float* w_pre_dw    = (const float*)d_in[5];
    const float* w_pre_pw    = (const float*)d_in[6];
    const float* w_proj      = (const float*)d_in[7];
    const float* ln_gamma    = (const float*)d_in[8];
    const float* ln_beta     = (const float*)d_in[9];

    float* out_h  = (float*)d_out;
    float* out_mp = out_h + (size_t)B_ * L_ * D_;

    cudaFuncSetAttribute(stage2_kernel,
                         cudaFuncAttributeMaxDynamicSharedMemorySize,
                         S2_SMEM_BYTES);

    dim3 g1(T_ / TILE, B_);
    stage1_kernel<<<g1, NTHR1>>>((const float4*)X, (const float4*)M,
                                 w_env, w_burst, synergy_raw,
                                 w_pre_dw, w_pre_pw, out_mp);
    stage2_kernel<<<S2GRID, S2T, S2_SMEM_BYTES>>>(w_proj, ln_gamma, ln_beta, out_h);
}

// round 11
// speedup vs baseline: 2.0618x; 1.2206x over previous
#include <cuda_runtime.h>
#include <cstdint>
#include <stdint.h>
#include <math.h>

#define B_    64
#define T_    50000
#define D_    160
#define PATCH 25
#define L_    2000
#define KENV  25
#define KBUR  9
#define KPRE  9

#define TILE  500
#define NTHR1 128

// residue-array strides (u64 units), padded to scatter banks
#define SXN   137
#define SDXN  133
#define SS0N  129

// ---- stage2 config ----
#define S2T     512
#define NR2     128
#define NT2     1000
#define AROW    100
#define S2GRID  148
#define S2ABUF  (NR2*AROW)
#define S2_SMEM_BYTES (16000*4 + 2*S2ABUF*4)

typedef unsigned long long u64;
typedef unsigned int u32;

__device__ float4 g_xs[(size_t)B_ * T_];

__device__ __forceinline__ u64 f2fma(u64 a, u64 b, u64 c) {
    u64 d; asm("fma.rn.f32x2 %0,%1,%2,%3;" : "=l"(d) : "l"(a), "l"(b), "l"(c)); return d;
}
__device__ __forceinline__ u64 f2add(u64 a, u64 b) {
    u64 d; asm("add.rn.f32x2 %0,%1,%2;" : "=l"(d) : "l"(a), "l"(b)); return d;
}
__device__ __forceinline__ u64 dup2(float x) {
    u64 r; asm("mov.b64 %0,{%1,%1};" : "=l"(r) : "f"(x)); return r;
}
__device__ __forceinline__ u64 pack2(float a, float b) {
    u64 r; asm("mov.b64 %0,{%1,%2};" : "=l"(r) : "f"(a), "f"(b)); return r;
}
__device__ __forceinline__ void unpack2(u64 v, float& lo, float& hi) {
    asm("mov.b64 {%0,%1},%2;" : "=f"(lo), "=f"(hi) : "l"(v));
}
__device__ __forceinline__ float softplusf_(float v) {
    return fmaxf(v, 0.0f) + log1pf(expf(-fabsf(v)));
}
__device__ __forceinline__ float gelu_exact(float v) { return v * normcdff(v); }

__device__ __forceinline__ void cpasync16(u32 dst, const void* src) {
    asm volatile("cp.async.cg.shared.global [%0], [%1], 16;" :: "r"(dst), "l"(src));
}
#define CP_COMMIT() asm volatile("cp.async.commit_group;")
#define CP_WAIT1()  asm volatile("cp.async.wait_group 1;")

// ---------------------------------------------------------------------------
// Stage 1: fused front pipeline. Residue-split smem: array[pp][t&3][t>>2]
// so that 4-points-per-thread tap loads are stride-8B (conflict-minimal).
// ---------------------------------------------------------------------------
__global__ __launch_bounds__(NTHR1) void stage1_kernel(
    const float4* __restrict__ X, const float4* __restrict__ M,
    const float*  __restrict__ w_env, const float* __restrict__ w_burst,
    const float*  __restrict__ synergy_raw, const float* __restrict__ w_pre_dw,
    const float*  __restrict__ w_pre_pw, float* __restrict__ out_mpatch)
{
    __shared__ u64 sx_r  [2][4][SXN];   // x = X*M, logical j = t-(t0-16), 532 used
    __shared__ u64 sabs_r[2][4][SXN];   // |x|
    __shared__ u64 sdx_r [2][4][SDXN];  // |dx|, logical i = t-(t0-8), 516 used
    __shared__ u64 sS0_r [2][4][SS0N];  // S0,  logical i = t-(t0-4), 508 used
    __shared__ unsigned smask_r[4][126];
    __shared__ float smt[TILE];
    __shared__ u64 swe_p[2][KENV], swb_p[2][KBUR], swd_p[2][KPRE];
    __shared__ float4 slut[16];
    __shared__ float  slmt[16];

    const int tid  = threadIdx.x;
    const int tile = blockIdx.x;
    const int b    = blockIdx.y;
    const int t0   = tile * TILE;

    float Wm[4][4];
    #pragma unroll
    for (int m = 0; m < 4; m++) {
        float r0 = softplusf_(synergy_raw[m*4+0]);
        float r1 = softplusf_(synergy_raw[m*4+1]);
        float r2 = softplusf_(synergy_raw[m*4+2]);
        float r3 = softplusf_(synergy_raw[m*4+3]);
        float inv = 1.0f / fmaxf(r0+r1+r2+r3, 1e-6f);
        Wm[m][0]=r0*inv; Wm[m][1]=r1*inv; Wm[m][2]=r2*inv; Wm[m][3]=r3*inv;
    }
    u64 Wp01[4], Wp23[4], pw01[4], pw23[4];
    #pragma unroll
    for (int c = 0; c < 4; c++) {
        Wp01[c] = pack2(Wm[0][c], Wm[1][c]);
        Wp23[c] = pack2(Wm[2][c], Wm[3][c]);
        pw01[c] = pack2(w_pre_pw[0*4+c], w_pre_pw[1*4+c]);
        pw23[c] = pack2(w_pre_pw[2*4+c], w_pre_pw[3*4+c]);
    }

    if (tid < KENV) {
        swe_p[0][tid] = pack2(0.9f*w_env[tid],    0.9f*w_env[25+tid]);
        swe_p[1][tid] = pack2(0.9f*w_env[50+tid], 0.9f*w_env[75+tid]);
    }
    if (tid < KBUR) {
        swb_p[0][tid] = pack2(0.6f*w_burst[tid],    0.6f*w_burst[9+tid]);
        swb_p[1][tid] = pack2(0.6f*w_burst[18+tid], 0.6f*w_burst[27+tid]);
        swd_p[0][tid] = pack2(w_pre_dw[tid],    w_pre_dw[9+tid]);
        swd_p[1][tid] = pack2(w_pre_dw[18+tid], w_pre_dw[27+tid]);
    }
    if (tid < 16) {
        float mm[4]; float4 sv;
        #pragma unroll
        for (int c = 0; c < 4; c++) mm[c] = (float)((tid >> c) & 1);
        float v0 = Wm[0][0]*mm[0]+Wm[0][1]*mm[1]+Wm[0][2]*mm[2]+Wm[0][3]*mm[3];
        float v1 = Wm[1][0]*mm[0]+Wm[1][1]*mm[1]+Wm[1][2]*mm[2]+Wm[1][3]*mm[3];
        float v2 = Wm[2][0]*mm[0]+Wm[2][1]*mm[1]+Wm[2][2]*mm[2]+Wm[2][3]*mm[3];
        float v3 = Wm[3][0]*mm[0]+Wm[3][1]*mm[1]+Wm[3][2]*mm[2]+Wm[3][3]*mm[3];
        sv.x = fminf(fmaxf(v0,0.f),1.f); sv.y = fminf(fmaxf(v1,0.f),1.f);
        sv.z = fminf(fmaxf(v2,0.f),1.f); sv.w = fminf(fmaxf(v3,0.f),1.f);
        slut[tid] = sv;
        slmt[tid] = ((sv.x+sv.y+sv.z+sv.w) > 0.f) ? 1.f : 0.f;
    }

    // Phase A: x = X*M, |x|, mask bits -> residue arrays
    const float4* Xb = X + (size_t)b * T_;
    const float4* Mb = M + (size_t)b * T_;
    for (int j = tid; j < TILE + 32; j += NTHR1) {
        int t = t0 - 16 + j;
        u64 x01 = 0, x23 = 0, a01 = 0, a23 = 0;
        if (t >= 0 && t < T_) {
            float4 X4 = Xb[t], M4 = Mb[t];
            float xx = X4.x*M4.x, xy = X4.y*M4.y, xz = X4.z*M4.z, xw = X4.w*M4.w;
            x01 = pack2(xx, xy); x23 = pack2(xz, xw);
            a01 = pack2(fabsf(xx), fabsf(xy)); a23 = pack2(fabsf(xz), fabsf(xw));
            if (j >= 16 && j < 16 + TILE) {
                unsigned mk = (M4.x > 0.f ? 1u : 0u) | (M4.y > 0.f ? 2u : 0u)
                            | (M4.z > 0.f ? 4u : 0u) | (M4.w > 0.f ? 8u : 0u);
                smask_r[(j-16)&3][(j-16)>>2] = mk;
            }
        }
        int jr = j & 3, jq = j >> 2;
        sx_r[0][jr][jq] = x01;  sx_r[1][jr][jq] = x23;
        sabs_r[0][jr][jq] = a01; sabs_r[1][jr][jq] = a23;
    }
    __syncthreads();

    // Phase dx: |x[t]-x[t-1]|
    for (int i = tid; i < TILE + 16; i += NTHR1) {
        int t = t0 - 8 + i;
        u64 r01 = 0, r23 = 0;
        if (t >= 1 && t < T_) {
            int ja = i + 8, jc = i + 7;
            u64 a01 = sx_r[0][ja&3][ja>>2], a23 = sx_r[1][ja&3][ja>>2];
            u64 c01 = sx_r[0][jc&3][jc>>2], c23 = sx_r[1][jc&3][jc>>2];
            float ax, ay, az, aw, cx, cy, cz, cw;
            unpack2(a01, ax, ay); unpack2(a23, az, aw);
            unpack2(c01, cx, cy); unpack2(c23, cz, cw);
            r01 = pack2(fabsf(ax-cx), fabsf(ay-cy));
            r23 = pack2(fabsf(az-cz), fabsf(aw-cw));
        }
        sdx_r[0][i&3][i>>2] = r01; sdx_r[1][i&3][i>>2] = r23;
    }
    __syncthreads();

    const u64 c02 = pack2(0.2f, 0.2f);

    // Phase B: env(25) + burst(9) + 0.2x, synergy mix -> sS0. 4 pts/thread.
    // Tap j = 4*tid + k: array [k&3], index tid + (k>>2) -> stride-8B lanes.
    if (tid < 127) {
        u64 xm[2][4];
        #pragma unroll
        for (int pp = 0; pp < 2; pp++) {
            u64 e0=0,e1=0,e2=0,e3=0;
            u64 d0 = sabs_r[pp][0][tid];
            u64 d1 = sabs_r[pp][1][tid];
            u64 d2 = sabs_r[pp][2][tid];
            #pragma unroll
            for (int k = 0; k < KENV; k++) {
                u64 w  = swe_p[pp][k];
                u64 d3 = sabs_r[pp][(k+3)&3][tid + ((k+3)>>2)];
                e0 = f2fma(d0,w,e0); e1 = f2fma(d1,w,e1);
                e2 = f2fma(d2,w,e2); e3 = f2fma(d3,w,e3);
                d0 = d1; d1 = d2; d2 = d3;
            }
            u64 u0=0,u1=0,u2=0,u3=0;
            d0 = sdx_r[pp][0][tid];
            d1 = sdx_r[pp][1][tid];
            d2 = sdx_r[pp][2][tid];
            #pragma unroll
            for (int k = 0; k < KBUR; k++) {
                u64 w  = swb_p[pp][k];
                u64 d3 = sdx_r[pp][(k+3)&3][tid + ((k+3)>>2)];
                u0 = f2fma(d0,w,u0); u1 = f2fma(d1,w,u1);
                u2 = f2fma(d2,w,u2); u3 = f2fma(d3,w,u3);
                d0 = d1; d1 = d2; d2 = d3;
            }
            // 0.2*x at logical j = 4tid + 12 + r: array r, index tid+3
            xm[pp][0] = f2fma(sx_r[pp][0][tid+3], c02, f2add(e0,u0));
            xm[pp][1] = f2fma(sx_r[pp][1][tid+3], c02, f2add(e1,u1));
            xm[pp][2] = f2fma(sx_r[pp][2][tid+3], c02, f2add(e2,u2));
            xm[pp][3] = f2fma(sx_r[pp][3][tid+3], c02, f2add(e3,u3));
        }
        #pragma unroll
        for (int r = 0; r < 4; r++) {
            float m0,m1,m2,m3;
            unpack2(xm[0][r], m0, m1); unpack2(xm[1][r], m2, m3);
            u64 dd0 = dup2(m0), dd1 = dup2(m1), dd2 = dup2(m2), dd3 = dup2(m3);
            u64 s01 = 0ull, s23 = 0ull;
            s01 = f2fma(dd0, Wp01[0], s01); s01 = f2fma(dd1, Wp01[1], s01);
            s01 = f2fma(dd2, Wp01[2], s01); s01 = f2fma(dd3, Wp01[3], s01);
            s23 = f2fma(dd0, Wp23[0], s23); s23 = f2fma(dd1, Wp23[1], s23);
            s23 = f2fma(dd2, Wp23[2], s23); s23 = f2fma(dd3, Wp23[3], s23);
            int tb = t0 - 4 + 4*tid + r;
            if (tb < 0 || tb >= T_) { s01 = 0ull; s23 = 0ull; }
            sS0_r[0][r][tid] = s01;
            sS0_r[1][r][tid] = s23;
        }
    }
    __syncthreads();

    // Phase C: dwconv K=9 + gelu, pointwise + gelu, mask, xs, m_time. 4 pts/thread.
    if (tid < 125) {
        const int i0 = 4 * tid;
        u64 aa[2][4];
        #pragma unroll
        for (int pp = 0; pp < 2; pp++) {
            u64 a0=0,a1=0,a2=0,a3=0;
            u64 d0 = sS0_r[pp][0][tid];
            u64 d1 = sS0_r[pp][1][tid];
            u64 d2 = sS0_r[pp][2][tid];
            #pragma unroll
            for (int k = 0; k < KPRE; k++) {
                u64 w  = swd_p[pp][k];
                u64 d3 = sS0_r[pp][(k+3)&3][tid + ((k+3)>>2)];
                a0 = f2fma(d0,w,a0); a1 = f2fma(d1,w,a1);
                a2 = f2fma(d2,w,a2); a3 = f2fma(d3,w,a3);
                d0 = d1; d1 = d2; d2 = d3;
            }
            aa[pp][0]=a0; aa[pp][1]=a1; aa[pp][2]=a2; aa[pp][3]=a3;
        }
        #pragma unroll
        for (int r = 0; r < 4; r++) {
            float g0,g1,g2,g3;
            unpack2(aa[0][r], g0, g1); unpack2(aa[1][r], g2, g3);
            float s1_0 = gelu_exact(g0), s1_1 = gelu_exact(g1);
            float s1_2 = gelu_exact(g2), s1_3 = gelu_exact(g3);

            u64 t01 = 0ull, t23 = 0ull;
            u64 e0 = dup2(s1_0), e1 = dup2(s1_1), e2 = dup2(s1_2), e3 = dup2(s1_3);
            t01 = f2fma(e0, pw01[0], t01); t01 = f2fma(e1, pw01[1], t01);
            t01 = f2fma(e2, pw01[2], t01); t01 = f2fma(e3, pw01[3], t01);
            t23 = f2fma(e0, pw23[0], t23); t23 = f2fma(e1, pw23[1], t23);
            t23 = f2fma(e2, pw23[2], t23); t23 = f2fma(e3, pw23[3], t23);
            float v0,v1,v2,v3;
            unpack2(t01, v0, v1); unpack2(t23, v2, v3);

            unsigned mk = smask_r[r][tid];
            float4 smv = slut[mk];
            float4 xs;
            xs.x = gelu_exact(v0) * smv.x;
            xs.y = gelu_exact(v1) * smv.y;
            xs.z = gelu_exact(v2) * smv.z;
            xs.w = gelu_exact(v3) * smv.w;
            g_xs[(size_t)b * T_ + t0 + i0 + r] = xs;
            smt[i0 + r] = slmt[mk];
        }
    }
    __syncthreads();

    // m_patch: 20 patches per tile
    if (tid < TILE / PATCH) {
        float s = 0.f;
        int base = tid * PATCH;
        #pragma unroll
        for (int p = 0; p < PATCH; p++) s += smt[base + p];
        out_mpatch[b * L_ + tile * (TILE/PATCH) + tid] =
            (s * (1.0f/25.0f) > 0.1f) ? 1.0f : 0.0f;
    }
}

// ---------------------------------------------------------------------------
// Stage 2: unchanged from R9 (103us). [128000x100]x[100x160] + LayerNorm.
// ---------------------------------------------------------------------------
__global__ __launch_bounds__(S2T, 1) void stage2_kernel(
    const float* __restrict__ w_proj, const float* __restrict__ ln_gamma,
    const float* __restrict__ ln_beta, float* __restrict__ out_h)
{
    extern __shared__ float sm2[];
    float* sW = sm2;
    float* sA = sm2 + 16000;

    const int tid = threadIdx.x;
    const int tx  = tid & 31;
    const int ty  = tid >> 5;

    for (int i = tid; i < 8000; i += S2T) {
        int kk = i / 160, d = i - kk*160;
        int k0 = 2*kk, k1 = 2*kk + 1;
        float2 w;
        w.x = w_proj[d*100 + (k0 & 3)*25 + (k0 >> 2)];
        w.y = w_proj[d*100 + (k1 & 3)*25 + (k1 >> 2)];
        *(float2*)&sW[2*i] = w;
    }
    float gam[5], bet[5];
    #pragma unroll
    for (int c = 0; c < 5; c++) { gam[c] = ln_gamma[tx + 32*c]; bet[c] = ln_beta[tx + 32*c]; }

    const float4* gxs = (const float4*)g_xs;
    u32 sA_u32;
    { void* p = sA; asm("{ .reg .u64 t; cvta.to.shared.u64 t, %1; cvt.u32.u64 %0, t; }"
                        : "=r"(sA_u32) : "l"(p)); }

    {
        int base = blockIdx.x * (NR2*25);
        #pragma unroll
        for (int it = 0; it < 7; it++) {
            int i = tid + it * S2T;
            if (i < NR2*25) {
                int r = i / 25, p = i - r*25;
                cpasync16(sA_u32 + (r*AROW + 4*p)*4, gxs + base + i);
            }
        }
        CP_COMMIT();
    }

    int cur = 0;
    for (int tt = blockIdx.x; tt < NT2; tt += S2GRID) {
        int nt = tt + S2GRID;
        if (nt < NT2) {
            int base = nt * (NR2*25);
            u32 dst = sA_u32 + (u32)(cur^1) * (S2ABUF*4);
            #pragma unroll
            for (int it = 0; it < 7; it++) {
                int i = tid + it * S2T;
                if (i < NR2*25) {
                    int r = i / 25, p = i - r*25;
                    cpasync16(dst + (r*AROW + 4*p)*4, gxs + base + i);
                }
            }
        }
        CP_COMMIT();
        CP_WAIT1();
        __syncthreads();

        u64 acc[8][5];
        #pragma unroll
        for (int r = 0; r < 8; r++)
            #pragma unroll
            for (int c = 0; c < 5; c++) acc[r][c] = 0ull;

        const float* aT = sA + cur * S2ABUF + (ty*8) * AROW;
        const u64*   wp = (const u64*)sW;

        #pragma unroll 10
        for (int kk = 0; kk < 50; kk++) {
            u64 wv[5];
            #pragma unroll
            for (int c = 0; c < 5; c++) wv[c] = wp[kk*160 + tx + 32*c];
            #pragma unroll
            for (int r = 0; r < 8; r++) {
                u64 av = *(const u64*)(aT + r*AROW + 2*kk);
                #pragma unroll
                for (int c = 0; c < 5; c++) acc[r][c] = f2fma(av, wv[c], acc[r][c]);
            }
        }

        #pragma unroll
        for (int r = 0; r < 8; r++) {
            float h[5]; float s = 0.f, q = 0.f;
            #pragma unroll
            for (int c = 0; c < 5; c++) {
                float lo, hi; unpack2(acc[r][c], lo, hi);
                h[c] = lo + hi;
                s += h[c]; q += h[c]*h[c];
            }
            #pragma unroll
            for (int off = 16; off > 0; off >>= 1) {
                s += __shfl_xor_sync(0xffffffffu, s, off);
                q += __shfl_xor_sync(0xffffffffu, q, off);
            }
            float mu = s * (1.0f/160.0f);
            float rs = rsqrtf(q * (1.0f/160.0f) - mu*mu + 1e-5f);
            int rg = tt*NR2 + ty*8 + r;
            float* o = out_h + (size_t)rg * D_ + tx;
            #pragma unroll
            for (int c = 0; c < 5; c++)
                o[32*c] = (h[c] - mu) * rs * gam[c] + bet[c];
        }
        __syncthreads();
        cur ^= 1;
    }
}

// ---------------------------------------------------------------------------
extern "C" void kernel_launch(void* const* d_in, const int* in_sizes, int n_in,
                              void* d_out, int out_size) {
    const float* X           = (const float*)d_in[0];
    const float* M           = (const float*)d_in[1];
    const float* w_env       = (const float*)d_in[2];
    const float* w_burst     = (const float*)d_in[3];
    const float* synergy_raw = (const float*)d_in[4];
    const float* w_pre_dw    = (const float*)d_in[5];
    const float* w_pre_pw    = (const float*)d_in[6];
    const float* w_proj      = (const float*)d_in[7];
    const float* ln_gamma    = (const float*)d_in[8];
    const float* ln_beta     = (const float*)d_in[9];

    float* out_h  = (float*)d_out;
    float* out_mp = out_h + (size_t)B_ * L_ * D_;

    cudaFuncSetAttribute(stage2_kernel,
                         cudaFuncAttributeMaxDynamicSharedMemorySize,
                         S2_SMEM_BYTES);

    dim3 g1(T_ / TILE, B_);
    stage1_kernel<<<g1, NTHR1>>>((const float4*)X, (const float4*)M,
                                 w_env, w_burst, synergy_raw,
                                 w_pre_dw, w_pre_pw, out_mp);
    stage2_kernel<<<S2GRID, S2T, S2_SMEM_BYTES>>>(w_proj, ln_gamma, ln_beta, out_h);
}

// round 12
// speedup vs baseline: 2.3162x; 1.1234x over previous
#include <cuda_runtime.h>
#include <cstdint>
#include <stdint.h>
#include <math.h>

#define B_    64
#define T_    50000
#define D_    160
#define PATCH 25
#define L_    2000
#define KENV  25
#define KBUR  9
#define KPRE  9

#define TILE  500
#define NTHR1 128

// residue-array strides (u64 units), padded to scatter banks
#define SXN   137
#define SDXN  133
#define SS0N  129

// ---- stage2 config ----
#define S2T     512
#define NR2     128
#define NT2     1000
#define AROW    100
#define S2GRID  148
#define S2ABUF  (NR2*AROW)
#define S2_SMEM_BYTES (16000*4 + 2*S2ABUF*4)

typedef unsigned long long u64;
typedef unsigned int u32;

__device__ float4 g_xs[(size_t)B_ * T_];

__device__ __forceinline__ u64 f2fma(u64 a, u64 b, u64 c) {
    u64 d; asm("fma.rn.f32x2 %0,%1,%2,%3;" : "=l"(d) : "l"(a), "l"(b), "l"(c)); return d;
}
__device__ __forceinline__ u64 f2add(u64 a, u64 b) {
    u64 d; asm("add.rn.f32x2 %0,%1,%2;" : "=l"(d) : "l"(a), "l"(b)); return d;
}
__device__ __forceinline__ u64 dup2(float x) {
    u64 r; asm("mov.b64 %0,{%1,%1};" : "=l"(r) : "f"(x)); return r;
}
__device__ __forceinline__ u64 pack2(float a, float b) {
    u64 r; asm("mov.b64 %0,{%1,%2};" : "=l"(r) : "f"(a), "f"(b)); return r;
}
__device__ __forceinline__ void unpack2(u64 v, float& lo, float& hi) {
    asm("mov.b64 {%0,%1},%2;" : "=f"(lo), "=f"(hi) : "l"(v));
}
__device__ __forceinline__ float softplusf_(float v) {
    return fmaxf(v, 0.0f) + log1pf(expf(-fabsf(v)));
}

// Branch-free exact-GELU: Phi via A&S 7.1.26 erf (abs err <= 1.5e-7).
__device__ __forceinline__ float gelu_fast(float x) {
    float z  = x * 0.70710678118654752f;
    float az = fabsf(z);
    float t  = __fdividef(1.0f, fmaf(0.3275911f, az, 1.0f));
    float p  = t * fmaf(t, fmaf(t, fmaf(t, fmaf(t, 1.061405429f, -1.453152027f),
                                        1.421413741f), -0.284496736f), 0.254829592f);
    float e  = __expf(-az * az);
    float erf_az = fmaf(-p, e, 1.0f);
    float erf_z  = copysignf(erf_az, z);
    return 0.5f * x * (1.0f + erf_z);
}

__device__ __forceinline__ void cpasync16(u32 dst, const void* src) {
    asm volatile("cp.async.cg.shared.global [%0], [%1], 16;" :: "r"(dst), "l"(src));
}
#define CP_COMMIT() asm volatile("cp.async.commit_group;")
#define CP_WAIT1()  asm volatile("cp.async.wait_group 1;")

// ---------------------------------------------------------------------------
// Stage 1: fused front pipeline. Residue-split smem: array[pp][t&3][t>>2]
// so that 4-points-per-thread tap loads are stride-8B (conflict-minimal).
// ---------------------------------------------------------------------------
__global__ __launch_bounds__(NTHR1) void stage1_kernel(
    const float4* __restrict__ X, const float4* __restrict__ M,
    const float*  __restrict__ w_env, const float* __restrict__ w_burst,
    const float*  __restrict__ synergy_raw, const float* __restrict__ w_pre_dw,
    const float*  __restrict__ w_pre_pw, float* __restrict__ out_mpatch)
{
    __shared__ u64 sx_r  [2][4][SXN];
    __shared__ u64 sabs_r[2][4][SXN];
    __shared__ u64 sdx_r [2][4][SDXN];
    __shared__ u64 sS0_r [2][4][SS0N];
    __shared__ unsigned smask_r[4][126];
    __shared__ float smt[TILE];
    __shared__ u64 swe_p[2][KENV], swb_p[2][KBUR], swd_p[2][KPRE];
    __shared__ float4 slut[16];
    __shared__ float  slmt[16];

    const int tid  = threadIdx.x;
    const int tile = blockIdx.x;
    const int b    = blockIdx.y;
    const int t0   = tile * TILE;

    float Wm[4][4];
    #pragma unroll
    for (int m = 0; m < 4; m++) {
        float r0 = softplusf_(synergy_raw[m*4+0]);
        float r1 = softplusf_(synergy_raw[m*4+1]);
        float r2 = softplusf_(synergy_raw[m*4+2]);
        float r3 = softplusf_(synergy_raw[m*4+3]);
        float inv = 1.0f / fmaxf(r0+r1+r2+r3, 1e-6f);
        Wm[m][0]=r0*inv; Wm[m][1]=r1*inv; Wm[m][2]=r2*inv; Wm[m][3]=r3*inv;
    }
    u64 Wp01[4], Wp23[4], pw01[4], pw23[4];
    #pragma unroll
    for (int c = 0; c < 4; c++) {
        Wp01[c] = pack2(Wm[0][c], Wm[1][c]);
        Wp23[c] = pack2(Wm[2][c], Wm[3][c]);
        pw01[c] = pack2(w_pre_pw[0*4+c], w_pre_pw[1*4+c]);
        pw23[c] = pack2(w_pre_pw[2*4+c], w_pre_pw[3*4+c]);
    }

    if (tid < KENV) {
        swe_p[0][tid] = pack2(0.9f*w_env[tid],    0.9f*w_env[25+tid]);
        swe_p[1][tid] = pack2(0.9f*w_env[50+tid], 0.9f*w_env[75+tid]);
    }
    if (tid < KBUR) {
        swb_p[0][tid] = pack2(0.6f*w_burst[tid],    0.6f*w_burst[9+tid]);
        swb_p[1][tid] = pack2(0.6f*w_burst[18+tid], 0.6f*w_burst[27+tid]);
        swd_p[0][tid] = pack2(w_pre_dw[tid],    w_pre_dw[9+tid]);
        swd_p[1][tid] = pack2(w_pre_dw[18+tid], w_pre_dw[27+tid]);
    }
    if (tid < 16) {
        float mm[4]; float4 sv;
        #pragma unroll
        for (int c = 0; c < 4; c++) mm[c] = (float)((tid >> c) & 1);
        float v0 = Wm[0][0]*mm[0]+Wm[0][1]*mm[1]+Wm[0][2]*mm[2]+Wm[0][3]*mm[3];
        float v1 = Wm[1][0]*mm[0]+Wm[1][1]*mm[1]+Wm[1][2]*mm[2]+Wm[1][3]*mm[3];
        float v2 = Wm[2][0]*mm[0]+Wm[2][1]*mm[1]+Wm[2][2]*mm[2]+Wm[2][3]*mm[3];
        float v3 = Wm[3][0]*mm[0]+Wm[3][1]*mm[1]+Wm[3][2]*mm[2]+Wm[3][3]*mm[3];
        sv.x = fminf(fmaxf(v0,0.f),1.f); sv.y = fminf(fmaxf(v1,0.f),1.f);
        sv.z = fminf(fmaxf(v2,0.f),1.f); sv.w = fminf(fmaxf(v3,0.f),1.f);
        slut[tid] = sv;
        slmt[tid] = ((sv.x+sv.y+sv.z+sv.w) > 0.f) ? 1.f : 0.f;
    }

    // Phase A: x = X*M, |x|, mask bits -> residue arrays
    const float4* Xb = X + (size_t)b * T_;
    const float4* Mb = M + (size_t)b * T_;
    for (int j = tid; j < TILE + 32; j += NTHR1) {
        int t = t0 - 16 + j;
        u64 x01 = 0, x23 = 0, a01 = 0, a23 = 0;
        if (t >= 0 && t < T_) {
            float4 X4 = Xb[t], M4 = Mb[t];
            float xx = X4.x*M4.x, xy = X4.y*M4.y, xz = X4.z*M4.z, xw = X4.w*M4.w;
            x01 = pack2(xx, xy); x23 = pack2(xz, xw);
            a01 = pack2(fabsf(xx), fabsf(xy)); a23 = pack2(fabsf(xz), fabsf(xw));
            if (j >= 16 && j < 16 + TILE) {
                unsigned mk = (M4.x > 0.f ? 1u : 0u) | (M4.y > 0.f ? 2u : 0u)
                            | (M4.z > 0.f ? 4u : 0u) | (M4.w > 0.f ? 8u : 0u);
                smask_r[(j-16)&3][(j-16)>>2] = mk;
            }
        }
        int jr = j & 3, jq = j >> 2;
        sx_r[0][jr][jq] = x01;  sx_r[1][jr][jq] = x23;
        sabs_r[0][jr][jq] = a01; sabs_r[1][jr][jq] = a23;
    }
    __syncthreads();

    // Phase dx: |x[t]-x[t-1]|
    for (int i = tid; i < TILE + 16; i += NTHR1) {
        int t = t0 - 8 + i;
        u64 r01 = 0, r23 = 0;
        if (t >= 1 && t < T_) {
            int ja = i + 8, jc = i + 7;
            u64 a01 = sx_r[0][ja&3][ja>>2], a23 = sx_r[1][ja&3][ja>>2];
            u64 c01 = sx_r[0][jc&3][jc>>2], c23 = sx_r[1][jc&3][jc>>2];
            float ax, ay, az, aw, cx, cy, cz, cw;
            unpack2(a01, ax, ay); unpack2(a23, az, aw);
            unpack2(c01, cx, cy); unpack2(c23, cz, cw);
            r01 = pack2(fabsf(ax-cx), fabsf(ay-cy));
            r23 = pack2(fabsf(az-cz), fabsf(aw-cw));
        }
        sdx_r[0][i&3][i>>2] = r01; sdx_r[1][i&3][i>>2] = r23;
    }
    __syncthreads();

    const u64 c02 = pack2(0.2f, 0.2f);

    // Phase B: env(25) + burst(9) + 0.2x, synergy mix -> sS0. 4 pts/thread.
    if (tid < 127) {
        u64 xm[2][4];
        #pragma unroll
        for (int pp = 0; pp < 2; pp++) {
            u64 e0=0,e1=0,e2=0,e3=0;
            u64 d0 = sabs_r[pp][0][tid];
            u64 d1 = sabs_r[pp][1][tid];
            u64 d2 = sabs_r[pp][2][tid];
            #pragma unroll
            for (int k = 0; k < KENV; k++) {
                u64 w  = swe_p[pp][k];
                u64 d3 = sabs_r[pp][(k+3)&3][tid + ((k+3)>>2)];
                e0 = f2fma(d0,w,e0); e1 = f2fma(d1,w,e1);
                e2 = f2fma(d2,w,e2); e3 = f2fma(d3,w,e3);
                d0 = d1; d1 = d2; d2 = d3;
            }
            u64 u0=0,u1=0,u2=0,u3=0;
            d0 = sdx_r[pp][0][tid];
            d1 = sdx_r[pp][1][tid];
            d2 = sdx_r[pp][2][tid];
            #pragma unroll
            for (int k = 0; k < KBUR; k++) {
                u64 w  = swb_p[pp][k];
                u64 d3 = sdx_r[pp][(k+3)&3][tid + ((k+3)>>2)];
                u0 = f2fma(d0,w,u0); u1 = f2fma(d1,w,u1);
                u2 = f2fma(d2,w,u2); u3 = f2fma(d3,w,u3);
                d0 = d1; d1 = d2; d2 = d3;
            }
            xm[pp][0] = f2fma(sx_r[pp][0][tid+3], c02, f2add(e0,u0));
            xm[pp][1] = f2fma(sx_r[pp][1][tid+3], c02, f2add(e1,u1));
            xm[pp][2] = f2fma(sx_r[pp][2][tid+3], c02, f2add(e2,u2));
            xm[pp][3] = f2fma(sx_r[pp][3][tid+3], c02, f2add(e3,u3));
        }
        #pragma unroll
        for (int r = 0; r < 4; r++) {
            float m0,m1,m2,m3;
            unpack2(xm[0][r], m0, m1); unpack2(xm[1][r], m2, m3);
            u64 dd0 = dup2(m0), dd1 = dup2(m1), dd2 = dup2(m2), dd3 = dup2(m3);
            u64 s01 = 0ull, s23 = 0ull;
            s01 = f2fma(dd0, Wp01[0], s01); s01 = f2fma(dd1, Wp01[1], s01);
            s01 = f2fma(dd2, Wp01[2], s01); s01 = f2fma(dd3, Wp01[3], s01);
            s23 = f2fma(dd0, Wp23[0], s23); s23 = f2fma(dd1, Wp23[1], s23);
            s23 = f2fma(dd2, Wp23[2], s23); s23 = f2fma(dd3, Wp23[3], s23);
            int tb = t0 - 4 + 4*tid + r;
            if (tb < 0 || tb >= T_) { s01 = 0ull; s23 = 0ull; }
            sS0_r[0][r][tid] = s01;
            sS0_r[1][r][tid] = s23;
        }
    }
    __syncthreads();

    // Phase C: dwconv K=9 + gelu, pointwise + gelu, mask, xs, m_time. 4 pts/thread.
    if (tid < 125) {
        const int i0 = 4 * tid;
        u64 aa[2][4];
        #pragma unroll
        for (int pp = 0; pp < 2; pp++) {
            u64 a0=0,a1=0,a2=0,a3=0;
            u64 d0 = sS0_r[pp][0][tid];
            u64 d1 = sS0_r[pp][1][tid];
            u64 d2 = sS0_r[pp][2][tid];
            #pragma unroll
            for (int k = 0; k < KPRE; k++) {
                u64 w  = swd_p[pp][k];
                u64 d3 = sS0_r[pp][(k+3)&3][tid + ((k+3)>>2)];
                a0 = f2fma(d0,w,a0); a1 = f2fma(d1,w,a1);
                a2 = f2fma(d2,w,a2); a3 = f2fma(d3,w,a3);
                d0 = d1; d1 = d2; d2 = d3;
            }
            aa[pp][0]=a0; aa[pp][1]=a1; aa[pp][2]=a2; aa[pp][3]=a3;
        }
        #pragma unroll
        for (int r = 0; r < 4; r++) {
            float g0,g1,g2,g3;
            unpack2(aa[0][r], g0, g1); unpack2(aa[1][r], g2, g3);
            float s1_0 = gelu_fast(g0), s1_1 = gelu_fast(g1);
            float s1_2 = gelu_fast(g2), s1_3 = gelu_fast(g3);

            u64 t01 = 0ull, t23 = 0ull;
            u64 e0 = dup2(s1_0), e1 = dup2(s1_1), e2 = dup2(s1_2), e3 = dup2(s1_3);
            t01 = f2fma(e0, pw01[0], t01); t01 = f2fma(e1, pw01[1], t01);
            t01 = f2fma(e2, pw01[2], t01); t01 = f2fma(e3, pw01[3], t01);
            t23 = f2fma(e0, pw23[0], t23); t23 = f2fma(e1, pw23[1], t23);
            t23 = f2fma(e2, pw23[2], t23); t23 = f2fma(e3, pw23[3], t23);
            float v0,v1,v2,v3;
            unpack2(t01, v0, v1); unpack2(t23, v2, v3);

            unsigned mk = smask_r[r][tid];
            float4 smv = slut[mk];
            float4 xs;
            xs.x = gelu_fast(v0) * smv.x;
            xs.y = gelu_fast(v1) * smv.y;
            xs.z = gelu_fast(v2) * smv.z;
            xs.w = gelu_fast(v3) * smv.w;
            g_xs[(size_t)b * T_ + t0 + i0 + r] = xs;
            smt[i0 + r] = slmt[mk];
        }
    }
    __syncthreads();

    // m_patch: 20 patches per tile
    if (tid < TILE / PATCH) {
        float s = 0.f;
        int base = tid * PATCH;
        #pragma unroll
        for (int p = 0; p < PATCH; p++) s += smt[base + p];
        out_mpatch[b * L_ + tile * (TILE/PATCH) + tid] =
            (s * (1.0f/25.0f) > 0.1f) ? 1.0f : 0.0f;
    }
}

// ---------------------------------------------------------------------------
// Stage 2: unchanged (103us). [128000x100]x[100x160] + LayerNorm.
// ---------------------------------------------------------------------------
__global__ __launch_bounds__(S2T, 1) void stage2_kernel(
    const float* __restrict__ w_proj, const float* __restrict__ ln_gamma,
    const float* __restrict__ ln_beta, float* __restrict__ out_h)
{
    extern __shared__ float sm2[];
    float* sW = sm2;
    float* sA = sm2 + 16000;

    const int tid = threadIdx.x;
    const int tx  = tid & 31;
    const int ty  = tid >> 5;

    for (int i = tid; i < 8000; i += S2T) {
        int kk = i / 160, d = i - kk*160;
        int k0 = 2*kk, k1 = 2*kk + 1;
        float2 w;
        w.x = w_proj[d*100 + (k0 & 3)*25 + (k0 >> 2)];
        w.y = w_proj[d*100 + (k1 & 3)*25 + (k1 >> 2)];
        *(float2*)&sW[2*i] = w;
    }
    float gam[5], bet[5];
    #pragma unroll
    for (int c = 0; c < 5; c++) { gam[c] = ln_gamma[tx + 32*c]; bet[c] = ln_beta[tx + 32*c]; }

    const float4* gxs = (const float4*)g_xs;
    u32 sA_u32;
    { void* p = sA; asm("{ .reg .u64 t; cvta.to.shared.u64 t, %1; cvt.u32.u64 %0, t; }"
                        : "=r"(sA_u32) : "l"(p)); }

    {
        int base = blockIdx.x * (NR2*25);
        #pragma unroll
        for (int it = 0; it < 7; it++) {
            int i = tid + it * S2T;
            if (i < NR2*25) {
                int r = i / 25, p = i - r*25;
                cpasync16(sA_u32 + (r*AROW + 4*p)*4, gxs + base + i);
            }
        }
        CP_COMMIT();
    }

    int cur = 0;
    for (int tt = blockIdx.x; tt < NT2; tt += S2GRID) {
        int nt = tt + S2GRID;
        if (nt < NT2) {
            int base = nt * (NR2*25);
            u32 dst = sA_u32 + (u32)(cur^1) * (S2ABUF*4);
            #pragma unroll
            for (int it = 0; it < 7; it++) {
                int i = tid + it * S2T;
                if (i < NR2*25) {
                    int r = i / 25, p = i - r*25;
                    cpasync16(dst + (r*AROW + 4*p)*4, gxs + base + i);
                }
            }
        }
        CP_COMMIT();
        CP_WAIT1();
        __syncthreads();

        u64 acc[8][5];
        #pragma unroll
        for (int r = 0; r < 8; r++)
            #pragma unroll
            for (int c = 0; c < 5; c++) acc[r][c] = 0ull;

        const float* aT = sA + cur * S2ABUF + (ty*8) * AROW;
        const u64*   wp = (const u64*)sW;

        #pragma unroll 10
        for (int kk = 0; kk < 50; kk++) {
            u64 wv[5];
            #pragma unroll
            for (int c = 0; c < 5; c++) wv[c] = wp[kk*160 + tx + 32*c];
            #pragma unroll
            for (int r = 0; r < 8; r++) {
                u64 av = *(const u64*)(aT + r*AROW + 2*kk);
                #pragma unroll
                for (int c = 0; c < 5; c++) acc[r][c] = f2fma(av, wv[c], acc[r][c]);
            }
        }

        #pragma unroll
        for (int r = 0; r < 8; r++) {
            float h[5]; float s = 0.f, q = 0.f;
            #pragma unroll
            for (int c = 0; c < 5; c++) {
                float lo, hi; unpack2(acc[r][c], lo, hi);
                h[c] = lo + hi;
                s += h[c]; q += h[c]*h[c];
            }
            #pragma unroll
            for (int off = 16; off > 0; off >>= 1) {
                s += __shfl_xor_sync(0xffffffffu, s, off);
                q += __shfl_xor_sync(0xffffffffu, q, off);
            }
            float mu = s * (1.0f/160.0f);
            float rs = rsqrtf(q * (1.0f/160.0f) - mu*mu + 1e-5f);
            int rg = tt*NR2 + ty*8 + r;
            float* o = out_h + (size_t)rg * D_ + tx;
            #pragma unroll
            for (int c = 0; c < 5; c++)
                o[32*c] = (h[c] - mu) * rs * gam[c] + bet[c];
        }
        __syncthreads();
        cur ^= 1;
    }
}

// ---------------------------------------------------------------------------
extern "C" void kernel_launch(void* const* d_in, const int* in_sizes, int n_in,
                              void* d_out, int out_size) {
    const float* X           = (const float*)d_in[0];
    const float* M           = (const float*)d_in[1];
    const float* w_env       = (const float*)d_in[2];
    const float* w_burst     = (const float*)d_in[3];
    const float* synergy_raw = (const float*)d_in[4];
    const float* w_pre_dw    = (const float*)d_in[5];
    const float* w_pre_pw    = (const float*)d_in[6];
    const float* w_proj      = (const float*)d_in[7];
    const float* ln_gamma    = (const float*)d_in[8];
    const float* ln_beta     = (const float*)d_in[9];

    float* out_h  = (float*)d_out;
    float* out_mp = out_h + (size_t)B_ * L_ * D_;

    cudaFuncSetAttribute(stage2_kernel,
                         cudaFuncAttributeMaxDynamicSharedMemorySize,
                         S2_SMEM_BYTES);

    dim3 g1(T_ / TILE, B_);
    stage1_kernel<<<g1, NTHR1>>>((const float4*)X, (const float4*)M,
                                 w_env, w_burst, synergy_raw,
                                 w_pre_dw, w_pre_pw, out_mp);
    stage2_kernel<<<S2GRID, S2T, S2_SMEM_BYTES>>>(w_proj, ln_gamma, ln_beta, out_h);
}